// round 15
// baseline (speedup 1.0000x reference)
#include <cuda_runtime.h>

// Problem constants (fixed by the reference)
#define NB        2000                  // N_BUSES
#define BATCH     32                    // B
#define NEDGE     6000                  // E per batch
#define TOT_NODES (BATCH * NB)          // 64000
#define TOT_EDGES (BATCH * NEDGE)       // 192000
#define HLOG2     14
#define HSLOTS    (1 << HLOG2)          // 16384 slots/batch, load 0.37 (proven)
#define HMASK     (HSLOTS - 1)
#define TOT_SLOTS (BATCH * HSLOTS)      // 524288 (4 MB, 64-bit entries)

// Static scratch — zero at module load. k_node clears the hash each call
// (AFTER the PDL sync), re-zeroes g_yv, and resets the accumulators: every
// call starts from zeroed state (deterministic across graph replays).
__device__ unsigned long long g_hash[TOT_SLOTS];  // (cell+1)<<32 | edge_id
__device__ float2             g_yv[TOT_NODES];    // YV (complex)
__device__ float              g_acc[5];           // d1r, d1i, d2, d3, mse
__device__ unsigned           g_count;            // finalize counter

__device__ __forceinline__ unsigned hash_cell(unsigned cell) {
    return (cell * 2654435761u) & HMASK;          // R6-proven
}

// ============ K1: single-pass scatter with last-write-wins compensation =====
// (R12-proven logic) Every edge adds its contribution immediately.
// Duplicates: atomicMax keeps max edge id per cell; observer of a same-cell
// conflict subtracts the LOSER's contribution. Net per cell = winner only
// == JAX .at[...].set semantics.
__global__ void k_edge(const int*   __restrict__ ei,
                       const float* __restrict__ ea,
                       const float* __restrict__ outs) {
    // PDL: fire IMMEDIATELY so the dependent k_node grid launches and runs its
    // independent prologue concurrently with this whole kernel. Memory safety
    // is carried by cudaGridDependencySynchronize() in k_node, which waits for
    // this grid's completion regardless of trigger placement.
    cudaTriggerProgrammaticLaunchCompletion();

    int t = blockIdx.x * blockDim.x + threadIdx.x;
    if (t < TOT_EDGES) {
        int b = t / NEDGE;
        int e = t - b * NEDGE;
        int i = ei[t] % NB;              if (i < 0) i += NB;
        int j = ei[TOT_EDGES + t] % NB;  if (j < 0) j += NB;

        float2 adm = ((const float2*)ea)[t];
        float2 v   = ((const float2*)outs)[b * NB + j];
        int ni = b * NB + i;
        // single vectorized 64-bit atomic (sm_90+): one RED.64 vs two RED.32
        atomicAdd(&g_yv[ni], make_float2(adm.x * v.x - adm.y * v.y,
                                         adm.x * v.y + adm.y * v.x));

        unsigned cell = (unsigned)(i * NB + j) + 1u;        // +1 so 0 == empty
        unsigned long long mine = ((unsigned long long)cell << 32) | (unsigned)e;
        unsigned h = hash_cell(cell);
        unsigned long long* tab = g_hash + ((size_t)b << HLOG2);

        while (true) {
            unsigned long long old = atomicCAS(&tab[h], 0ULL, mine);
            if (old == 0ULL) break;                          // unique so far
            if ((unsigned)(old >> 32) == cell) {             // duplicate cell
                unsigned long long m = atomicMax(&tab[h], mine);
                if (m != mine) {
                    unsigned long long loser = (m < mine) ? m : mine;
                    int el = (int)(unsigned)loser;           // losing edge id
                    // same cell => same (i, j) => same v
                    float2 adml = ((const float2*)ea)[b * NEDGE + el];
                    atomicAdd(&g_yv[ni],
                              make_float2(-(adml.x * v.x - adml.y * v.y),
                                          -(adml.x * v.y + adml.y * v.x)));
                }
                break;
            }
            h = (h + 1) & HMASK;                             // linear probe
        }
    }
}

// ========== K2: node terms + reduce + last-block finalize; self-clean =======
// Output: 5 float32 = real parts of (loss, physics_loss, d1, d2, d3).
// PDL-structured: everything independent of k_edge runs BEFORE the grid sync.
#define NTHR2 256
#define NBLK2 ((TOT_NODES + NTHR2 - 1) / NTHR2)   // 250

__global__ __launch_bounds__(NTHR2)
void k_node(const float* __restrict__ x,
            const float* __restrict__ outs,
            const float* __restrict__ labels,
            float* __restrict__ out, int nfloats) {
    int idx = blockIdx.x * NTHR2 + threadIdx.x;

    // ---- prologue: loads + terms independent of k_edge (overlaps k_edge) ----
    float a0 = 0.f, a1 = 0.f, a2 = 0.f, a3 = 0.f, a4 = 0.f;
    float2 v = make_float2(0.f, 0.f);
    float sr = 0.f, si = 0.f, b0 = 0.f, b1 = 0.f;
    if (idx < TOT_NODES) {
        v = ((const float2*)outs)[idx];

        const float2* nf2 = (const float2*)(x + 6 * idx);
        float2 p0 = nf2[0], p1 = nf2[1], p2 = nf2[2];
        sr = p0.x; si = p0.y;
        float Vm = p1.x;
        b0 = p1.y; b1 = p2.x;
        float b2 = p2.y;

        float vmag  = sqrtf(v.x * v.x + v.y * v.y);
        float vminv = 1.f / Vm;
        a2 = fabsf(vmag * (b1 + b2) - Vm) * vminv;
        a3 = fabsf(v.y * b2) * vminv;

        float2 lab = ((const float2*)labels)[idx];
        float e0 = v.x - lab.x;
        float e1 = v.y - lab.y;
        a4 = e0 * e0 + e1 * e1;
    }

    // ---- wait for k_edge's writes (g_yv, g_hash) to be visible ----
    cudaGridDependencySynchronize();

    // clear the hash for the next call (must be after the sync: k_edge still
    // probes the table until it completes)
    for (int s = idx; s < TOT_SLOTS; s += NTHR2 * NBLK2)
        g_hash[s] = 0ULL;

    if (idx < TOT_NODES) {
        float2 yv = __ldcg(&g_yv[idx]);                      // L2-written atomics
        g_yv[idx] = make_float2(0.f, 0.f);                   // self-clean

        // Spred = V * conj(YV)
        float spr = v.x * yv.x + v.y * yv.y;
        float spi = v.y * yv.x - v.x * yv.y;

        float dr = spr - sr;
        float di = spi - si;
        float sinv = rsqrtf(sr * sr + si * si);              // |1/S|

        a0 = sinv * ((dr * dr - di * di) * b0 + dr * dr * b1);
        a1 = sinv * (2.f * dr * di * b0);
    }

    // ---- reduction (proven pattern) ----
    #pragma unroll
    for (int o = 16; o > 0; o >>= 1) {
        a0 += __shfl_down_sync(0xFFFFFFFFu, a0, o);
        a1 += __shfl_down_sync(0xFFFFFFFFu, a1, o);
        a2 += __shfl_down_sync(0xFFFFFFFFu, a2, o);
        a3 += __shfl_down_sync(0xFFFFFFFFu, a3, o);
        a4 += __shfl_down_sync(0xFFFFFFFFu, a4, o);
    }

    __shared__ float sm[5][8];
    __shared__ bool  last;
    int lane = threadIdx.x & 31, warp = threadIdx.x >> 5;
    if (lane == 0) { sm[0][warp] = a0; sm[1][warp] = a1; sm[2][warp] = a2;
                     sm[3][warp] = a3; sm[4][warp] = a4; }
    __syncthreads();
    if (warp == 0) {
        float v0 = (lane < 8) ? sm[0][lane] : 0.f;
        float v1 = (lane < 8) ? sm[1][lane] : 0.f;
        float v2 = (lane < 8) ? sm[2][lane] : 0.f;
        float v3 = (lane < 8) ? sm[3][lane] : 0.f;
        float v4 = (lane < 8) ? sm[4][lane] : 0.f;
        #pragma unroll
        for (int o = 4; o > 0; o >>= 1) {
            v0 += __shfl_down_sync(0xFFFFFFFFu, v0, o);
            v1 += __shfl_down_sync(0xFFFFFFFFu, v1, o);
            v2 += __shfl_down_sync(0xFFFFFFFFu, v2, o);
            v3 += __shfl_down_sync(0xFFFFFFFFu, v3, o);
            v4 += __shfl_down_sync(0xFFFFFFFFu, v4, o);
        }
        if (lane == 0) {
            atomicAdd(&g_acc[0], v0);
            atomicAdd(&g_acc[1], v1);
            atomicAdd(&g_acc[2], v2);
            atomicAdd(&g_acc[3], v3);
            atomicAdd(&g_acc[4], v4);
            __threadfence();
            unsigned r = atomicAdd(&g_count, 1u);
            last = (r == (unsigned)(NBLK2 - 1));
        }
    }
    __syncthreads();

    if (last && threadIdx.x == 0) {
        float v0 = __ldcg(&g_acc[0]);
        float v1 = __ldcg(&g_acc[1]);
        float v2 = __ldcg(&g_acc[2]);
        float v3 = __ldcg(&g_acc[3]);
        float v4 = __ldcg(&g_acc[4]);
        const double inv = 1.0 / (double)TOT_NODES;
        double d1r = (double)v0 * inv;
        double d1i = (double)v1 * inv;
        double d2  = (double)v2 * inv;
        double d3  = (double)v3 * inv;
        double mse = (double)v4 / (double)(TOT_NODES * 2);
        double pr  = d1r + d2 + d3;
        double lr  = mse + 0.1 * pr;
        float vals[10] = { (float)lr, (float)pr, (float)d1r, (float)d2, (float)d3,
                           (float)(0.1 * d1i), (float)d1i, (float)d1i, 0.f, 0.f };
        for (int k = 0; k < nfloats && k < 10; k++) out[k] = vals[k];
        g_acc[0] = 0.f; g_acc[1] = 0.f; g_acc[2] = 0.f;
        g_acc[3] = 0.f; g_acc[4] = 0.f;
        g_count  = 0u;
    }
}

// ------------------------------------------------------------------ launcher
extern "C" void kernel_launch(void* const* d_in, const int* in_sizes, int n_in,
                              void* d_out, int out_size) {
    const float* x      = (const float*)d_in[0];   // (B*2000, 6)
    const float* ea     = (const float*)d_in[1];   // (B*6000, 2)
    const int*   ei     = (const int*)  d_in[2];   // (2, B*6000)
    const float* outs   = (const float*)d_in[3];   // (B*2000, 2)
    const float* labels = (const float*)d_in[4];   // (B*2000, 2)
    (void)in_sizes; (void)n_in;

    int nfloats = out_size < 10 ? out_size : 10;

    k_edge<<<(TOT_EDGES + 255) / 256, 256>>>(ei, ea, outs);

    // k_node with PDL: launches while k_edge runs; its pre-sync prologue
    // overlaps k_edge, and cudaGridDependencySynchronize guards g_yv/g_hash.
    cudaLaunchConfig_t cfg = {};
    cfg.gridDim  = dim3(NBLK2, 1, 1);
    cfg.blockDim = dim3(NTHR2, 1, 1);
    cfg.dynamicSmemBytes = 0;
    cfg.stream = 0;
    cudaLaunchAttribute attr[1];
    attr[0].id = cudaLaunchAttributeProgrammaticStreamSerialization;
    attr[0].val.programmaticStreamSerializationAllowed = 1;
    cfg.attrs = attr;
    cfg.numAttrs = 1;
    float* outp = (float*)d_out;
    cudaError_t err = cudaLaunchKernelEx(&cfg, k_node, x, outs, labels, outp, nfloats);
    if (err != cudaSuccess) {
        // fallback: plain serialized launch (reproduces proven R12 behavior;
        // the grid-dep sync is a no-op when not launched as dependent)
        k_node<<<NBLK2, NTHR2>>>(x, outs, labels, outp, nfloats);
    }
}

// round 16
// speedup vs baseline: 1.0894x; 1.0894x over previous
#include <cuda_runtime.h>

// Problem constants (fixed by the reference)
#define NB        2000                  // N_BUSES
#define BATCH     32                    // B
#define NEDGE     6000                  // E per batch
#define TOT_NODES (BATCH * NB)          // 64000
#define TOT_EDGES (BATCH * NEDGE)       // 192000
#define HLOG2     14
#define HSLOTS    (1 << HLOG2)          // 16384 slots/batch, load 0.37 (proven)
#define HMASK     (HSLOTS - 1)
#define TOT_SLOTS (BATCH * HSLOTS)      // 524288 (4 MB, 64-bit entries)

#define NTHR      256
#define NBLK_E    (TOT_EDGES / NTHR)    // 750  (edge kernel)
#define NBLK_N    (TOT_NODES / NTHR)    // 250  (node kernel; also the k_edge
                                        //       blocks that carry node terms)

// Static scratch — zero at module load. k_node clears the hash each call
// (AFTER the PDL sync), re-zeroes g_yv, finalize resets the accumulators:
// every call starts from zeroed state (deterministic across graph replays).
__device__ unsigned long long g_hash[TOT_SLOTS];  // (cell+1)<<32 | edge_id
__device__ float2             g_yv[TOT_NODES];    // YV (complex)
__device__ float              g_acc[5];           // d1r, d1i, d2, d3, mse
__device__ unsigned           g_count;            // finalize counter

__device__ __forceinline__ unsigned hash_cell(unsigned cell) {
    return (cell * 2654435761u) & HMASK;          // R6-proven
}

// ===== K1: compensated edge scatter + the k_edge-INDEPENDENT node terms =====
// Edge dedup (R12-proven): every edge adds its contribution; duplicates are
// resolved by hash atomicMax (max edge id wins == JAX .set), with the loser's
// contribution subtracted by whoever observes the conflict.
// Node terms d2/d3/mse depend only on inputs, so the first TOT_NODES threads
// compute and accumulate them here, overlapped with the edge work's latency.
__global__ __launch_bounds__(NTHR)
void k_edge(const int*   __restrict__ ei,
            const float* __restrict__ ea,
            const float* __restrict__ outs,
            const float* __restrict__ x,
            const float* __restrict__ labels) {
    // PDL: let the dependent k_node grid launch immediately; its grid-dep
    // sync carries all memory safety.
    cudaTriggerProgrammaticLaunchCompletion();

    const int t = blockIdx.x * NTHR + threadIdx.x;   // == edge id, < TOT_EDGES

    // ---- node-independent terms (blocks 0..NBLK_N-1 exactly) ----
    float a2 = 0.f, a3 = 0.f, a4 = 0.f;
    if (t < TOT_NODES) {
        float2 v = ((const float2*)outs)[t];
        const float2* nf2 = (const float2*)(x + 6 * t);
        float2 p1 = nf2[1], p2 = nf2[2];
        float Vm = p1.x, b1 = p2.x, b2 = p2.y;

        float vmag  = sqrtf(v.x * v.x + v.y * v.y);
        float vminv = 1.f / Vm;
        a2 = fabsf(vmag * (b1 + b2) - Vm) * vminv;
        a3 = fabsf(v.y * b2) * vminv;

        float2 lab = ((const float2*)labels)[t];
        float e0 = v.x - lab.x;
        float e1 = v.y - lab.y;
        a4 = e0 * e0 + e1 * e1;
    }

    // ---- compensated edge scatter (one edge per thread) ----
    {
        int b = t / NEDGE;
        int e = t - b * NEDGE;
        int i = ei[t] % NB;              if (i < 0) i += NB;
        int j = ei[TOT_EDGES + t] % NB;  if (j < 0) j += NB;

        float2 adm = ((const float2*)ea)[t];
        float2 v   = ((const float2*)outs)[b * NB + j];
        int ni = b * NB + i;
        atomicAdd(&g_yv[ni], make_float2(adm.x * v.x - adm.y * v.y,
                                         adm.x * v.y + adm.y * v.x));

        unsigned cell = (unsigned)(i * NB + j) + 1u;         // +1 so 0 == empty
        unsigned long long mine = ((unsigned long long)cell << 32) | (unsigned)e;
        unsigned h = hash_cell(cell);
        unsigned long long* tab = g_hash + ((size_t)b << HLOG2);

        while (true) {
            unsigned long long old = atomicCAS(&tab[h], 0ULL, mine);
            if (old == 0ULL) break;                          // unique so far
            if ((unsigned)(old >> 32) == cell) {             // duplicate cell
                unsigned long long m = atomicMax(&tab[h], mine);
                if (m != mine) {
                    unsigned long long loser = (m < mine) ? m : mine;
                    int el = (int)(unsigned)loser;           // losing edge id
                    float2 adml = ((const float2*)ea)[b * NEDGE + el];
                    atomicAdd(&g_yv[ni],
                              make_float2(-(adml.x * v.x - adml.y * v.y),
                                          -(adml.x * v.y + adml.y * v.x)));
                }
                break;
            }
            h = (h + 1) & HMASK;                             // linear probe
        }
    }

    // ---- reduce + accumulate node terms (only blocks that carry them) ----
    if (blockIdx.x < NBLK_N) {
        #pragma unroll
        for (int o = 16; o > 0; o >>= 1) {
            a2 += __shfl_down_sync(0xFFFFFFFFu, a2, o);
            a3 += __shfl_down_sync(0xFFFFFFFFu, a3, o);
            a4 += __shfl_down_sync(0xFFFFFFFFu, a4, o);
        }
        __shared__ float sm[3][8];
        int lane = threadIdx.x & 31, warp = threadIdx.x >> 5;
        if (lane == 0) { sm[0][warp] = a2; sm[1][warp] = a3; sm[2][warp] = a4; }
        __syncthreads();
        if (warp == 0) {
            float v2 = (lane < 8) ? sm[0][lane] : 0.f;
            float v3 = (lane < 8) ? sm[1][lane] : 0.f;
            float v4 = (lane < 8) ? sm[2][lane] : 0.f;
            #pragma unroll
            for (int o = 4; o > 0; o >>= 1) {
                v2 += __shfl_down_sync(0xFFFFFFFFu, v2, o);
                v3 += __shfl_down_sync(0xFFFFFFFFu, v3, o);
                v4 += __shfl_down_sync(0xFFFFFFFFu, v4, o);
            }
            if (lane == 0) {
                atomicAdd(&g_acc[2], v2);
                atomicAdd(&g_acc[3], v3);
                atomicAdd(&g_acc[4], v4);
            }
        }
    }
}

// ===== K2 (slim): d1 terms + finalize; PDL-overlapped operand prefetch ======
// Output: 5 float32 = real parts of (loss, physics_loss, d1, d2, d3).
__global__ __launch_bounds__(NTHR)
void k_node(const float* __restrict__ x,
            const float* __restrict__ outs,
            float* __restrict__ out, int nfloats) {
    const int idx = blockIdx.x * NTHR + threadIdx.x;         // < TOT_NODES

    // ---- prologue (overlaps k_edge via PDL): prefetch input operands ----
    float2 v = ((const float2*)outs)[idx];
    const float2* nf2 = (const float2*)(x + 6 * idx);
    float2 p0 = nf2[0];
    float  b0 = nf2[1].y;
    float  b1 = nf2[2].x;
    float  sr = p0.x, si = p0.y;
    float  sinv = rsqrtf(sr * sr + si * si);                 // |1/S|

    // ---- wait for k_edge's writes (g_yv, g_hash, g_acc[2..4]) ----
    cudaGridDependencySynchronize();

    float2 yv = __ldcg(&g_yv[idx]);                          // L2-written atomics
    g_yv[idx] = make_float2(0.f, 0.f);                       // self-clean

    // Spred = V * conj(YV)
    float spr = v.x * yv.x + v.y * yv.y;
    float spi = v.y * yv.x - v.x * yv.y;
    float dr = spr - sr;
    float di = spi - si;
    float a0 = sinv * ((dr * dr - di * di) * b0 + dr * dr * b1);
    float a1 = sinv * (2.f * dr * di * b0);

    // ---- 2-value reduction + last-block finalize (proven pattern) ----
    #pragma unroll
    for (int o = 16; o > 0; o >>= 1) {
        a0 += __shfl_down_sync(0xFFFFFFFFu, a0, o);
        a1 += __shfl_down_sync(0xFFFFFFFFu, a1, o);
    }
    __shared__ float sm[2][8];
    __shared__ bool  last;
    int lane = threadIdx.x & 31, warp = threadIdx.x >> 5;
    if (lane == 0) { sm[0][warp] = a0; sm[1][warp] = a1; }
    __syncthreads();
    if (warp == 0) {
        float v0 = (lane < 8) ? sm[0][lane] : 0.f;
        float v1 = (lane < 8) ? sm[1][lane] : 0.f;
        #pragma unroll
        for (int o = 4; o > 0; o >>= 1) {
            v0 += __shfl_down_sync(0xFFFFFFFFu, v0, o);
            v1 += __shfl_down_sync(0xFFFFFFFFu, v1, o);
        }
        if (lane == 0) {
            atomicAdd(&g_acc[0], v0);
            atomicAdd(&g_acc[1], v1);
            __threadfence();
            unsigned r = atomicAdd(&g_count, 1u);
            last = (r == (unsigned)(NBLK_N - 1));
        }
    }
    __syncthreads();

    if (last && threadIdx.x == 0) {
        float v0 = __ldcg(&g_acc[0]);
        float v1 = __ldcg(&g_acc[1]);
        float v2 = __ldcg(&g_acc[2]);
        float v3 = __ldcg(&g_acc[3]);
        float v4 = __ldcg(&g_acc[4]);
        const double inv = 1.0 / (double)TOT_NODES;
        double d1r = (double)v0 * inv;
        double d1i = (double)v1 * inv;
        double d2  = (double)v2 * inv;
        double d3  = (double)v3 * inv;
        double mse = (double)v4 / (double)(TOT_NODES * 2);
        double pr  = d1r + d2 + d3;
        double lr  = mse + 0.1 * pr;
        float vals[10] = { (float)lr, (float)pr, (float)d1r, (float)d2, (float)d3,
                           (float)(0.1 * d1i), (float)d1i, (float)d1i, 0.f, 0.f };
        for (int k = 0; k < nfloats && k < 10; k++) out[k] = vals[k];
        g_acc[0] = 0.f; g_acc[1] = 0.f; g_acc[2] = 0.f;
        g_acc[3] = 0.f; g_acc[4] = 0.f;
        g_count  = 0u;
    }

    // ---- hash clear, off the finalize critical path (vectorized) ----
    {
        ulonglong2* h2 = (ulonglong2*)g_hash;
        const ulonglong2 z = make_ulonglong2(0ULL, 0ULL);
        for (int s = idx; s < TOT_SLOTS / 2; s += NTHR * NBLK_N)
            h2[s] = z;
    }
}

// ------------------------------------------------------------------ launcher
extern "C" void kernel_launch(void* const* d_in, const int* in_sizes, int n_in,
                              void* d_out, int out_size) {
    const float* x      = (const float*)d_in[0];   // (B*2000, 6)
    const float* ea     = (const float*)d_in[1];   // (B*6000, 2)
    const int*   ei     = (const int*)  d_in[2];   // (2, B*6000)
    const float* outs   = (const float*)d_in[3];   // (B*2000, 2)
    const float* labels = (const float*)d_in[4];   // (B*2000, 2)
    (void)in_sizes; (void)n_in;

    int nfloats = out_size < 10 ? out_size : 10;

    k_edge<<<NBLK_E, NTHR>>>(ei, ea, outs, x, labels);

    // k_node with PDL: launches while k_edge runs; prologue overlaps k_edge,
    // cudaGridDependencySynchronize guards g_yv/g_hash/g_acc[2..4].
    cudaLaunchConfig_t cfg = {};
    cfg.gridDim  = dim3(NBLK_N, 1, 1);
    cfg.blockDim = dim3(NTHR, 1, 1);
    cfg.dynamicSmemBytes = 0;
    cfg.stream = 0;
    cudaLaunchAttribute attr[1];
    attr[0].id = cudaLaunchAttributeProgrammaticStreamSerialization;
    attr[0].val.programmaticStreamSerializationAllowed = 1;
    cfg.attrs = attr;
    cfg.numAttrs = 1;
    float* outp = (float*)d_out;
    cudaError_t err = cudaLaunchKernelEx(&cfg, k_node, x, outs, outp, nfloats);
    if (err != cudaSuccess) {
        // fallback: plain serialized launch (grid-dep sync is a no-op then)
        k_node<<<NBLK_N, NTHR>>>(x, outs, outp, nfloats);
    }
}

// round 17
// speedup vs baseline: 1.2920x; 1.1860x over previous
#include <cuda_runtime.h>

// Problem constants (fixed by the reference)
#define NB        2000                  // N_BUSES
#define BATCH     32                    // B
#define NEDGE     6000                  // E per batch
#define TOT_NODES (BATCH * NB)          // 64000
#define TOT_EDGES (BATCH * NEDGE)       // 192000
#define HLOG2     14
#define HSLOTS    (1 << HLOG2)          // 16384 slots, load 0.37 (proven ratio)
#define HMASK     (HSLOTS - 1)
#define NTHR      1024

// Persistent state: ONLY the accumulators + counter (reset by finalize).
__device__ float    g_acc[5];           // d1r, d1i, d2, d3, mse
__device__ unsigned g_count;            // last-block counter

// Dynamic smem layout (per block = per batch):
//   [0,      131072)  hash: 16384 x u64   ((cell+1)<<32 | edge_id)
//   [131072, 147456)  V:    2048 x float2 (2000 used)
//   [147456, 163456)  YV:   2000 x float2
#define SMEM_BYTES (HSLOTS * 8 + 2048 * 8 + NB * 8)

__device__ __forceinline__ unsigned hash_cell(unsigned cell) {
    return (cell * 2654435761u) & HMASK;          // R6-proven
}

// ================= the whole pipeline, one block per batch ==================
// Output: 5 float32 = real parts of (loss, physics_loss, d1, d2, d3).
__global__ __launch_bounds__(NTHR, 1)
void k_all(const float* __restrict__ x,
           const float* __restrict__ ea,
           const int*   __restrict__ ei,
           const float* __restrict__ outs,
           const float* __restrict__ labels,
           float* __restrict__ out, int nfloats) {
    extern __shared__ char smem[];
    unsigned long long* hash = (unsigned long long*)smem;
    float2* V  = (float2*)(smem + HSLOTS * 8);
    float2* YV = V + 2048;

    const int b   = blockIdx.x;                   // one block == one batch
    const int tid = threadIdx.x;

    // ---- phase A: clear hash + YV, stage V ----
    {
        ulonglong2* h2 = (ulonglong2*)hash;
        #pragma unroll
        for (int s = tid; s < HSLOTS / 2; s += NTHR)
            h2[s] = make_ulonglong2(0ULL, 0ULL);
    }
    for (int n = tid; n < NB; n += NTHR) {
        V[n]  = ((const float2*)outs)[b * NB + n];
        YV[n] = make_float2(0.f, 0.f);
    }
    __syncthreads();

    // ---- phase B: compensated edge scatter (R12-proven dedup, smem) ----
    // Every edge adds its contribution to smem YV; duplicate cells resolved by
    // hash atomicMax (max edge id wins == JAX .at[].set); observer of a
    // conflict subtracts the loser's contribution. Net per cell = winner only.
    for (int e = tid; e < NEDGE; e += NTHR) {
        int t = b * NEDGE + e;
        int i = ei[t] % NB;              if (i < 0) i += NB;
        int j = ei[TOT_EDGES + t] % NB;  if (j < 0) j += NB;

        float2 adm = ((const float2*)ea)[t];
        float2 v   = V[j];
        atomicAdd(&YV[i].x, adm.x * v.x - adm.y * v.y);
        atomicAdd(&YV[i].y, adm.x * v.y + adm.y * v.x);

        unsigned cell = (unsigned)(i * NB + j) + 1u;         // +1 so 0 == empty
        unsigned long long mine = ((unsigned long long)cell << 32) | (unsigned)e;
        unsigned h = hash_cell(cell);

        while (true) {
            unsigned long long old = atomicCAS(&hash[h], 0ULL, mine);
            if (old == 0ULL) break;                          // unique so far
            if ((unsigned)(old >> 32) == cell) {             // duplicate cell
                unsigned long long m = atomicMax(&hash[h], mine);
                if (m != mine) {
                    unsigned long long loser = (m < mine) ? m : mine;
                    int el = (int)(unsigned)loser;           // losing edge id
                    float2 adml = ((const float2*)ea)[b * NEDGE + el];
                    atomicAdd(&YV[i].x, -(adml.x * v.x - adml.y * v.y));
                    atomicAdd(&YV[i].y, -(adml.x * v.y + adml.y * v.x));
                }
                break;
            }
            h = (h + 1) & HMASK;                             // linear probe
        }
    }
    __syncthreads();

    // ---- phase C: per-node physics + MSE terms (2 nodes/thread) ----
    float a0 = 0.f, a1 = 0.f, a2 = 0.f, a3 = 0.f, a4 = 0.f;
    for (int n = tid; n < NB; n += NTHR) {
        int idx = b * NB + n;
        float2 v  = V[n];
        float2 yv = YV[n];

        // Spred = V * conj(YV)
        float spr = v.x * yv.x + v.y * yv.y;
        float spi = v.y * yv.x - v.x * yv.y;

        const float2* nf2 = (const float2*)(x + 6 * idx);
        float2 p0 = nf2[0], p1 = nf2[1], p2 = nf2[2];
        float sr = p0.x, si = p0.y, Vm = p1.x;
        float b0 = p1.y, b1 = p2.x, b2 = p2.y;

        float dr = spr - sr;
        float di = spi - si;
        float sinv = rsqrtf(sr * sr + si * si);              // |1/S|

        a0 += sinv * ((dr * dr - di * di) * b0 + dr * dr * b1);
        a1 += sinv * (2.f * dr * di * b0);

        float vmag  = sqrtf(v.x * v.x + v.y * v.y);
        float vminv = 1.f / Vm;
        a2 += fabsf(vmag * (b1 + b2) - Vm) * vminv;
        a3 += fabsf(v.y * b2) * vminv;

        float2 lab = ((const float2*)labels)[idx];
        float e0 = v.x - lab.x;
        float e1 = v.y - lab.y;
        a4 += e0 * e0 + e1 * e1;
    }

    // ---- phase D: block reduce (32 warps) + global accumulate + finalize ----
    #pragma unroll
    for (int o = 16; o > 0; o >>= 1) {
        a0 += __shfl_down_sync(0xFFFFFFFFu, a0, o);
        a1 += __shfl_down_sync(0xFFFFFFFFu, a1, o);
        a2 += __shfl_down_sync(0xFFFFFFFFu, a2, o);
        a3 += __shfl_down_sync(0xFFFFFFFFu, a3, o);
        a4 += __shfl_down_sync(0xFFFFFFFFu, a4, o);
    }

    __shared__ float sm[5][32];
    __shared__ bool  last;
    int lane = tid & 31, warp = tid >> 5;
    if (lane == 0) { sm[0][warp] = a0; sm[1][warp] = a1; sm[2][warp] = a2;
                     sm[3][warp] = a3; sm[4][warp] = a4; }
    __syncthreads();
    if (warp == 0) {
        float v0 = sm[0][lane];
        float v1 = sm[1][lane];
        float v2 = sm[2][lane];
        float v3 = sm[3][lane];
        float v4 = sm[4][lane];
        #pragma unroll
        for (int o = 16; o > 0; o >>= 1) {
            v0 += __shfl_down_sync(0xFFFFFFFFu, v0, o);
            v1 += __shfl_down_sync(0xFFFFFFFFu, v1, o);
            v2 += __shfl_down_sync(0xFFFFFFFFu, v2, o);
            v3 += __shfl_down_sync(0xFFFFFFFFu, v3, o);
            v4 += __shfl_down_sync(0xFFFFFFFFu, v4, o);
        }
        if (lane == 0) {
            atomicAdd(&g_acc[0], v0);
            atomicAdd(&g_acc[1], v1);
            atomicAdd(&g_acc[2], v2);
            atomicAdd(&g_acc[3], v3);
            atomicAdd(&g_acc[4], v4);
            __threadfence();
            unsigned r = atomicAdd(&g_count, 1u);
            last = (r == (unsigned)(BATCH - 1));
        }
    }
    __syncthreads();

    // last block finalizes + resets the (only) persistent state
    if (last && tid == 0) {
        float v0 = __ldcg(&g_acc[0]);
        float v1 = __ldcg(&g_acc[1]);
        float v2 = __ldcg(&g_acc[2]);
        float v3 = __ldcg(&g_acc[3]);
        float v4 = __ldcg(&g_acc[4]);
        const double inv = 1.0 / (double)TOT_NODES;
        double d1r = (double)v0 * inv;
        double d1i = (double)v1 * inv;
        double d2  = (double)v2 * inv;
        double d3  = (double)v3 * inv;
        double mse = (double)v4 / (double)(TOT_NODES * 2);
        double pr  = d1r + d2 + d3;
        double lr  = mse + 0.1 * pr;
        float vals[10] = { (float)lr, (float)pr, (float)d1r, (float)d2, (float)d3,
                           (float)(0.1 * d1i), (float)d1i, (float)d1i, 0.f, 0.f };
        for (int k = 0; k < nfloats && k < 10; k++) out[k] = vals[k];
        g_acc[0] = 0.f; g_acc[1] = 0.f; g_acc[2] = 0.f;
        g_acc[3] = 0.f; g_acc[4] = 0.f;
        g_count  = 0u;
    }
}

// ------------------------------------------------------------------ launcher
extern "C" void kernel_launch(void* const* d_in, const int* in_sizes, int n_in,
                              void* d_out, int out_size) {
    const float* x      = (const float*)d_in[0];   // (B*2000, 6)
    const float* ea     = (const float*)d_in[1];   // (B*6000, 2)
    const int*   ei     = (const int*)  d_in[2];   // (2, B*6000)
    const float* outs   = (const float*)d_in[3];   // (B*2000, 2)
    const float* labels = (const float*)d_in[4];   // (B*2000, 2)
    (void)in_sizes; (void)n_in;

    int nfloats = out_size < 10 ? out_size : 10;

    static int smem_configured = 0;                // host-side, not device state
    if (!smem_configured) {
        cudaFuncSetAttribute(k_all, cudaFuncAttributeMaxDynamicSharedMemorySize,
                             SMEM_BYTES);
        smem_configured = 1;
    }

    k_all<<<BATCH, NTHR, SMEM_BYTES>>>(x, ea, ei, outs, labels,
                                       (float*)d_out, nfloats);
}